// round 1
// baseline (speedup 1.0000x reference)
#include <cuda_runtime.h>
#include <math.h>

#define NT  365
#define NS  256
#define NH  256
#define NG  32
#define NR  16
#define HID 256
#define NTS (NT*NS)          // 93440
#define TOUT (NT-NR+1)       // 350

// ---------------- scratch (device globals; no allocation allowed) ----------
__device__ float g_hidden[NTS*HID];   // fcT layer-1 output (tanh)
__device__ float g_Pl[NTS*NH];
__device__ float g_Ev[NTS*NH];
__device__ float g_Vm[NTS*NH];
__device__ float g_Q[NTS*NH];
__device__ float g_hidW[NS*HID];
__device__ float g_hidR[NS*HID];
__device__ float g_baseT[NS*HID];     // xc-part of fcT layer 1 (pre-tanh)
__device__ float g_w[NS*NH*7];        // fcW layer-2 raw output
__device__ float g_rfraw[NS*NH*NR];   // fcR layer-2 raw output
__device__ float g_kp[NS*NH], g_ks[NS*NH], g_kg[NS*NH], g_gp[NS*NH];
__device__ float g_gL[NS*NH], g_qb[NS*NH], g_ga[NS*NH];
__device__ float g_r[NS*NH*NR];       // routing softmax weights
__device__ float g_Ps[NTS];           // snowfall P*vf
__device__ float g_pfrac[NTS];        // P*(1-vf)

__device__ __forceinline__ float sigf(float x){ return 1.0f/(1.0f+expf(-x)); }

// ---------------- kernel 1: snow partition ---------------------------------
__global__ void prep_kernel(const float* __restrict__ x){
    int i = blockIdx.x*blockDim.x + threadIdx.x;
    if (i >= NTS) return;
    float P  = x[i*6+0];
    float T1 = x[i*6+2];
    float T2 = x[i*6+3];
    float ratio = (T1+T2)/(T2-T1);
    ratio = fminf(fmaxf(ratio,-1.0f),1.0f);
    float vf = acosf(ratio)/3.1415f;
    if (T1 >= 0.0f) vf = 0.0f;
    if (T2 <= 0.0f) vf = 1.0f;
    g_Ps[i]    = P*vf;
    g_pfrac[i] = P*(1.0f-vf);
}

// ---------------- kernel 2: all xc-based layer-1s --------------------------
// mode 0: hidW = tanh(xc@fcW_w1+b1); mode 1: hidR; mode 2: baseT = xc@fcT_w1[6:]+b1 (no tanh)
__global__ void layer1_kernel(const float* __restrict__ xc,
                              const float* __restrict__ wW1, const float* __restrict__ bW1,
                              const float* __restrict__ wR1, const float* __restrict__ bR1,
                              const float* __restrict__ wT1, const float* __restrict__ bT1){
    int s = blockIdx.x, h = threadIdx.x, mode = blockIdx.y;
    __shared__ float xs[NG];
    if (h < NG) xs[h] = xc[s*NG + h];
    __syncthreads();
    const float* w; const float* b; float* out; bool dotanh;
    if (mode == 0){ w = wW1;         b = bW1; out = g_hidW;  dotanh = true;  }
    else if (mode == 1){ w = wR1;    b = bR1; out = g_hidR;  dotanh = true;  }
    else { w = wT1 + 6*HID;          b = bT1; out = g_baseT; dotanh = false; }
    float acc = b[h];
    #pragma unroll
    for (int g = 0; g < NG; g++) acc += xs[g]*w[g*HID + h];
    out[s*HID + h] = dotanh ? tanhf(acc) : acc;
}

// ---------------- kernel 3: fcT layer-1 per timestep ------------------------
__global__ void hiddenT_kernel(const float* __restrict__ x, const float* __restrict__ wT1){
    int row = blockIdx.x;           // t*NS + s
    int h   = threadIdx.x;
    int s   = row & (NS-1);
    __shared__ float xr[6];
    if (h < 6) xr[h] = x[row*6 + h];
    __syncthreads();
    float acc = g_baseT[s*HID + h];
    #pragma unroll
    for (int i = 0; i < 6; i++) acc += xr[i]*wT1[i*HID + h];
    g_hidden[row*HID + h] = tanhf(acc);
}

// ---------------- kernel 4: generic tiled fp32 GEMM (K=256) ----------------
// WHICH 0: g_hidW @ B -> g_w          [256 x 1792]
// WHICH 1: g_hidR @ B -> g_rfraw      [256 x 4096]
// WHICH 2: g_hidden @ B -> fused Pl/Ev/Vm epilogue   [93440 x 768]
#define BM 128
#define BN 64
#define BK 32
#define KK 256

template<int WHICH>
__global__ void __launch_bounds__(256) gemm_kernel(const float* __restrict__ B,
                                                   const float* __restrict__ bias,
                                                   const float* __restrict__ x){
    const float* A; float* C; int N;
    if (WHICH == 0){ A = g_hidW;   C = g_w;     N = NH*7;  }
    else if (WHICH == 1){ A = g_hidR; C = g_rfraw; N = NH*NR; }
    else { A = g_hidden; C = nullptr; N = NH*3; }

    __shared__ float As[2][BK][BM];
    __shared__ float Bs[2][BK][BN];

    const int tid = threadIdx.x;
    const int tx  = tid & 15;      // 16 col groups of 4
    const int ty  = tid >> 4;      // 16 row groups of 8
    const int bn  = blockIdx.x;
    const int bm  = blockIdx.y;

    const float* Ag = A + bm*BM*KK;
    const float* Bg = B + bn*BN;

    float acc[8][4];
    #pragma unroll
    for (int i = 0; i < 8; i++)
        #pragma unroll
        for (int j = 0; j < 4; j++) acc[i][j] = 0.0f;

    float4 ra[4], rb[2];

    auto ldg_tile = [&](int k0){
        #pragma unroll
        for (int i = 0; i < 4; i++){
            int f = tid + i*256;
            int row = f >> 3, c4 = f & 7;
            ra[i] = *(const float4*)(Ag + row*KK + k0 + c4*4);
        }
        #pragma unroll
        for (int i = 0; i < 2; i++){
            int f = tid + i*256;
            int row = f >> 4, c4 = f & 15;
            rb[i] = *(const float4*)(Bg + (k0 + row)*N + c4*4);
        }
    };
    auto sts_tile = [&](int buf){
        #pragma unroll
        for (int i = 0; i < 4; i++){
            int f = tid + i*256;
            int row = f >> 3, c4 = f & 7;
            As[buf][c4*4+0][row] = ra[i].x;
            As[buf][c4*4+1][row] = ra[i].y;
            As[buf][c4*4+2][row] = ra[i].z;
            As[buf][c4*4+3][row] = ra[i].w;
        }
        #pragma unroll
        for (int i = 0; i < 2; i++){
            int f = tid + i*256;
            int row = f >> 4, c4 = f & 15;
            *(float4*)&Bs[buf][row][c4*4] = rb[i];
        }
    };

    ldg_tile(0);
    sts_tile(0);
    __syncthreads();

    const int KT = KK/BK;
    int buf = 0;
    for (int kt = 0; kt < KT; kt++){
        if (kt + 1 < KT) ldg_tile((kt+1)*BK);
        #pragma unroll
        for (int k = 0; k < BK; k++){
            float4 a0 = *(const float4*)&As[buf][k][ty*8];
            float4 a1 = *(const float4*)&As[buf][k][ty*8+4];
            float4 b0 = *(const float4*)&Bs[buf][k][tx*4];
            float a[8] = {a0.x,a0.y,a0.z,a0.w,a1.x,a1.y,a1.z,a1.w};
            float b[4] = {b0.x,b0.y,b0.z,b0.w};
            #pragma unroll
            for (int i = 0; i < 8; i++)
                #pragma unroll
                for (int j = 0; j < 4; j++)
                    acc[i][j] += a[i]*b[j];
        }
        if (kt + 1 < KT){
            sts_tile(buf^1);
            __syncthreads();
            buf ^= 1;
        }
    }

    if (WHICH != 2){
        #pragma unroll
        for (int i = 0; i < 8; i++){
            int gr = bm*BM + ty*8 + i;
            #pragma unroll
            for (int j = 0; j < 4; j++){
                int gc = bn*BN + tx*4 + j;
                C[gr*N + gc] = acc[i][j] + bias[gc];
            }
        }
    } else {
        const int grp = bn >> 2;   // 4 blocks of 64 cols per 256-col group
        #pragma unroll
        for (int i = 0; i < 8; i++){
            int gr = bm*BM + ty*8 + i;
            float pf = 0.0f, Ee = 0.0f;
            if (grp == 0) pf = g_pfrac[gr];
            if (grp == 1) Ee = x[gr*6 + 1];
            #pragma unroll
            for (int j = 0; j < 4; j++){
                int gc = bn*BN + tx*4 + j;
                int h  = gc & (NH-1);
                float v = acc[i][j] + bias[gc];
                int oix = gr*NH + h;
                if (grp == 0){
                    float vi = fminf(fmaxf(v*(2.0f/6.0f)+0.5f, 0.0f), 1.0f);
                    g_Pl[oix] = pf*vi;
                } else if (grp == 1){
                    g_Ev[oix] = Ee*fmaxf(v, 0.0f)*2.0f;
                } else {
                    g_Vm[oix] = expf(v);
                }
            }
        }
    }
}

// ---------------- kernel 5: fcW activations + ga softmax --------------------
__global__ void actW_kernel(){
    int s = blockIdx.x, h = threadIdx.x;
    const float* w = g_w + s*(NH*7);
    float kp = sigf(w[h]);
    float ks = sigf(w[NH+h]);
    float kg = sigf(w[2*NH+h])/10.0f;
    float gp = sigf(w[3*NH+h]);
    float e  = expf(w[4*NH+h]);
    float gL = e*e;
    float qb = fmaxf(w[5*NH+h], 0.0f);
    float gar = w[6*NH+h];

    __shared__ float red[8];
    // block max
    float m = gar;
    #pragma unroll
    for (int o = 16; o; o >>= 1) m = fmaxf(m, __shfl_xor_sync(0xffffffffu, m, o));
    if ((h & 31) == 0) red[h>>5] = m;
    __syncthreads();
    if (h < 32){
        float v = (h < 8) ? red[h] : -1e30f;
        #pragma unroll
        for (int o = 4; o; o >>= 1) v = fmaxf(v, __shfl_xor_sync(0xffffffffu, v, o));
        if (h == 0) red[0] = v;
    }
    __syncthreads();
    float M = red[0];
    __syncthreads();
    float eg = expf(gar - M);
    // block sum
    float sm = eg;
    #pragma unroll
    for (int o = 16; o; o >>= 1) sm += __shfl_xor_sync(0xffffffffu, sm, o);
    if ((h & 31) == 0) red[h>>5] = sm;
    __syncthreads();
    if (h < 32){
        float v = (h < 8) ? red[h] : 0.0f;
        #pragma unroll
        for (int o = 4; o; o >>= 1) v += __shfl_xor_sync(0xffffffffu, v, o);
        if (h == 0) red[0] = v;
    }
    __syncthreads();
    float S = red[0];

    int ix = s*NH + h;
    g_kp[ix] = kp; g_ks[ix] = ks; g_kg[ix] = kg; g_gp[ix] = gp;
    g_gL[ix] = gL; g_qb[ix] = qb; g_ga[ix] = eg/S;
}

// ---------------- kernel 6: fcR relu + softmax over NR ----------------------
__global__ void actR_kernel(){
    int s = blockIdx.x, h = threadIdx.x;
    const float* rf = g_rfraw + s*(NH*NR) + h*NR;
    float v[NR];
    float m = -1e30f;
    #pragma unroll
    for (int j = 0; j < NR; j++){ v[j] = fmaxf(rf[j], 0.0f); m = fmaxf(m, v[j]); }
    float ssum = 0.0f;
    #pragma unroll
    for (int j = 0; j < NR; j++){ v[j] = expf(v[j]-m); ssum += v[j]; }
    float* out = g_r + s*(NH*NR) + h*NR;
    #pragma unroll
    for (int j = 0; j < NR; j++) out[j] = v[j]/ssum;
}

// ---------------- kernel 7: sequential reservoir scan -----------------------
__global__ void scan_kernel(){
    int s = blockIdx.x, h = threadIdx.x;
    int idx0 = s*NH + h;
    float kp = g_kp[idx0], ks = g_ks[idx0], kg = g_kg[idx0];
    float gp = g_gp[idx0], gL = g_gL[idx0], qb = g_qb[idx0];
    float Sf = 0.0f, Ss = 0.0f, Sg = 0.0f;

    int ix = idx0;
    float fl0 = g_Pl[ix], fev0 = g_Ev[ix], fm0 = g_Vm[ix];
    for (int t = 0; t < NT; t++){
        float fl = fl0, fev = fev0, fm = fm0;
        int ixc = ix;
        if (t + 1 < NT){
            ix += NS*NH;
            fl0 = g_Pl[ix]; fev0 = g_Ev[ix]; fm0 = g_Vm[ix];
        }
        float fs = g_Ps[t*NS + s];
        float a  = Sf + fs;
        float qf = fminf(a, fm);
        Sf = fmaxf(a - fm, 0.0f);
        float H  = fmaxf(Ss + fl + qf - fev, 0.0f);
        float qp = fmaxf(kp*(H - gL), 0.0f);
        float qsa = ks*fminf(H, gL);
        Ss = H - qp - qsa;
        float sgin = Sg + qsa*gp;
        float qg = kg*sgin + qb;
        Sg = (1.0f - kg)*sgin - qb;
        g_Q[ixc] = qp + qsa*(1.0f - gp) + qg;
    }
}

// ---------------- kernel 8: 16-tap conv + ga-weighted reduce ----------------
__global__ void conv_kernel(float* __restrict__ out){
    int s = blockIdx.x, h = threadIdx.x;
    float rr[NR];
    const float* rp = g_r + s*(NH*NR) + h*NR;
    #pragma unroll
    for (int j = 0; j < NR; j++) rr[j] = rp[j];
    float gah = g_ga[s*NH + h];
    int base = s*NH + h;

    float win[NR];
    #pragma unroll
    for (int j = 0; j < NR; j++) win[j] = g_Q[j*NS*NH + base];

    __shared__ float red[8];
    for (int tb = 0; tb < 352; tb += 16){
        #pragma unroll
        for (int tt = 0; tt < 16; tt++){
            int t = tb + tt;
            if (t < TOUT){
                float z = 0.0f;
                #pragma unroll
                for (int j = 0; j < NR; j++) z += rr[j]*win[(tt + j) & 15];
                float val = gah*z;
                #pragma unroll
                for (int o = 16; o; o >>= 1) val += __shfl_xor_sync(0xffffffffu, val, o);
                if ((h & 31) == 0) red[h>>5] = val;
                __syncthreads();
                if (h < 32){
                    float v = (h < 8) ? red[h] : 0.0f;
                    v += __shfl_xor_sync(0xffffffffu, v, 4);
                    v += __shfl_xor_sync(0xffffffffu, v, 2);
                    v += __shfl_xor_sync(0xffffffffu, v, 1);
                    if (h == 0) out[t*NS + s] = v;
                }
                __syncthreads();
                if (t + NR < NT) win[tt] = g_Q[(t + NR)*NS*NH + base];
            }
        }
    }
}

// ---------------- launch ----------------------------------------------------
extern "C" void kernel_launch(void* const* d_in, const int* in_sizes, int n_in,
                              void* d_out, int out_size){
    const float* x      = (const float*)d_in[0];
    const float* xc     = (const float*)d_in[1];
    const float* fcW_w1 = (const float*)d_in[2];
    const float* fcW_b1 = (const float*)d_in[3];
    const float* fcW_w2 = (const float*)d_in[4];
    const float* fcW_b2 = (const float*)d_in[5];
    const float* fcT_w1 = (const float*)d_in[6];
    const float* fcT_b1 = (const float*)d_in[7];
    const float* fcT_w2 = (const float*)d_in[8];
    const float* fcT_b2 = (const float*)d_in[9];
    const float* fcR_w1 = (const float*)d_in[10];
    const float* fcR_b1 = (const float*)d_in[11];
    const float* fcR_w2 = (const float*)d_in[12];
    const float* fcR_b2 = (const float*)d_in[13];
    float* out = (float*)d_out;

    prep_kernel<<<(NTS + 255)/256, 256>>>(x);
    layer1_kernel<<<dim3(NS, 3), 256>>>(xc, fcW_w1, fcW_b1, fcR_w1, fcR_b1, fcT_w1, fcT_b1);
    gemm_kernel<0><<<dim3((NH*7)/BN,  NS/BM),  256>>>(fcW_w2, fcW_b2, x);
    gemm_kernel<1><<<dim3((NH*NR)/BN, NS/BM),  256>>>(fcR_w2, fcR_b2, x);
    actW_kernel<<<NS, 256>>>();
    actR_kernel<<<NS, 256>>>();
    hiddenT_kernel<<<NTS, 256>>>(x, fcT_w1);
    gemm_kernel<2><<<dim3((NH*3)/BN,  NTS/BM), 256>>>(fcT_w2, fcT_b2, x);
    scan_kernel<<<NS, 256>>>();
    conv_kernel<<<NS, 256>>>(out);
}

// round 3
// speedup vs baseline: 1.9595x; 1.9595x over previous
#include <cuda_runtime.h>
#include <cstdint>
#include <math.h>

#define NT  365
#define NS  256
#define NH  256
#define NG  32
#define NR  16
#define HID 256
#define NTS (NT*NS)          // 93440
#define TOUT (NT-NR+1)       // 350
#define MTILES 730           // 93440/128

// ---------------- scratch (device globals; no allocation allowed) ----------
__device__ float g_hidden[NTS*HID];   // fcT layer-1 output (tanh, tf32-rounded)
__device__ float g_Pl[NTS*NH];
__device__ float g_Ev[NTS*NH];
__device__ float g_Vm[NTS*NH];
__device__ float g_Q[NTS*NH];
__device__ float g_hidW[NS*HID];
__device__ float g_hidR[NS*HID];
__device__ float g_baseT[NS*HID];     // xc-part of fcT layer 1 (pre-tanh)
__device__ float g_w[NS*NH*7];        // fcW layer-2 raw output
__device__ float g_rfraw[NS*NH*NR];   // fcR layer-2 raw output
__device__ float g_kp[NS*NH], g_ks[NS*NH], g_kg[NS*NH], g_gp[NS*NH];
__device__ float g_gL[NS*NH], g_qb[NS*NH], g_ga[NS*NH];
__device__ float g_r[NS*NH*NR];       // routing softmax weights
__device__ float g_Ps[NTS];           // snowfall P*vf
__device__ float g_pfrac[NTS];        // P*(1-vf)
__device__ float g_w2t[768*HID];      // fcT_w2 transposed: [N=768, K=256], tf32-rounded

__device__ __forceinline__ float sigf(float x){ return 1.0f/(1.0f+expf(-x)); }

__device__ __forceinline__ uint32_t smem_u32(const void* p){
    uint32_t a;
    asm("{ .reg .u64 t; cvta.to.shared.u64 t, %1; cvt.u32.u64 %0, t; }" : "=r"(a) : "l"(p));
    return a;
}
__device__ __forceinline__ float tf32r(float f){
    uint32_t u;
    asm("cvt.rna.tf32.f32 %0, %1;" : "=r"(u) : "f"(f));
    return __uint_as_float(u);
}
__device__ __forceinline__ void cpa16(uint32_t dst, const void* src){
    asm volatile("cp.async.cg.shared.global [%0], [%1], 16;" :: "r"(dst), "l"(src) : "memory");
}
#define CP_COMMIT() asm volatile("cp.async.commit_group;" ::: "memory")
template<int N> __device__ __forceinline__ void cpwait(){
    asm volatile("cp.async.wait_group %0;" :: "n"(N) : "memory");
}
#define LDSM_X4(r0,r1,r2,r3,addr) \
    asm volatile("ldmatrix.sync.aligned.m8n8.x4.shared.b16 {%0,%1,%2,%3}, [%4];" \
        : "=r"(r0),"=r"(r1),"=r"(r2),"=r"(r3) : "r"(addr))
#define MMA_TF32(c0,c1,c2,c3,a0,a1,a2,a3,b0,b1) \
    asm volatile("mma.sync.aligned.m16n8k8.row.col.f32.tf32.tf32.f32 " \
        "{%0,%1,%2,%3}, {%4,%5,%6,%7}, {%8,%9}, {%0,%1,%2,%3};" \
        : "+f"(c0),"+f"(c1),"+f"(c2),"+f"(c3) \
        : "r"(a0),"r"(a1),"r"(a2),"r"(a3), "r"(b0),"r"(b1))

// ---------------- kernel 1: snow partition ---------------------------------
__global__ void prep_kernel(const float* __restrict__ x){
    int i = blockIdx.x*blockDim.x + threadIdx.x;
    if (i >= NTS) return;
    float P  = x[i*6+0];
    float T1 = x[i*6+2];
    float T2 = x[i*6+3];
    float ratio = (T1+T2)/(T2-T1);
    ratio = fminf(fmaxf(ratio,-1.0f),1.0f);
    float vf = acosf(ratio)/3.1415f;
    if (T1 >= 0.0f) vf = 0.0f;
    if (T2 <= 0.0f) vf = 1.0f;
    g_Ps[i]    = P*vf;
    g_pfrac[i] = P*(1.0f-vf);
}

// ---------------- transpose fcT_w2 [256,768] -> g_w2t [768,256] (tf32) -----
__global__ void transposeB_kernel(const float* __restrict__ w2){
    __shared__ float t[32][33];
    int nb = blockIdx.x*32, kb = blockIdx.y*32;
    int tx = threadIdx.x & 31, ty = threadIdx.x >> 5;  // 256 threads: 32x8
    #pragma unroll
    for (int r = 0; r < 32; r += 8)
        t[ty+r][tx] = w2[(kb+ty+r)*768 + nb + tx];
    __syncthreads();
    #pragma unroll
    for (int r = 0; r < 32; r += 8)
        g_w2t[(nb+ty+r)*HID + kb + tx] = tf32r(t[tx][ty+r]);
}

// ---------------- kernel 2: all xc-based layer-1s --------------------------
__global__ void layer1_kernel(const float* __restrict__ xc,
                              const float* __restrict__ wW1, const float* __restrict__ bW1,
                              const float* __restrict__ wR1, const float* __restrict__ bR1,
                              const float* __restrict__ wT1, const float* __restrict__ bT1){
    int s = blockIdx.x, h = threadIdx.x, mode = blockIdx.y;
    __shared__ float xs[NG];
    if (h < NG) xs[h] = xc[s*NG + h];
    __syncthreads();
    const float* w; const float* b; float* out; bool dotanh;
    if (mode == 0){ w = wW1;         b = bW1; out = g_hidW;  dotanh = true;  }
    else if (mode == 1){ w = wR1;    b = bR1; out = g_hidR;  dotanh = true;  }
    else { w = wT1 + 6*HID;          b = bT1; out = g_baseT; dotanh = false; }
    float acc = b[h];
    #pragma unroll
    for (int g = 0; g < NG; g++) acc += xs[g]*w[g*HID + h];
    out[s*HID + h] = dotanh ? tanhf(acc) : acc;
}

// ---------------- kernel 3: fcT layer-1 per timestep (tf32-rounded) ---------
__global__ void hiddenT_kernel(const float* __restrict__ x, const float* __restrict__ wT1){
    int row = blockIdx.x;           // t*NS + s
    int h   = threadIdx.x;
    int s   = row & (NS-1);
    __shared__ float xr[6];
    if (h < 6) xr[h] = x[row*6 + h];
    __syncthreads();
    float acc = g_baseT[s*HID + h];
    #pragma unroll
    for (int i = 0; i < 6; i++) acc += xr[i]*wT1[i*HID + h];
    g_hidden[row*HID + h] = tf32r(tanhf(acc));
}

// ---------------- small SIMT GEMMs (fcW / fcR layer 2) -----------------------
#define BM 128
#define BN 64
#define BK 32
#define KK 256

template<int WHICH>
__global__ void __launch_bounds__(256) gemm_kernel(const float* __restrict__ B,
                                                   const float* __restrict__ bias){
    const float* A; float* C; int N;
    if (WHICH == 0){ A = g_hidW;   C = g_w;     N = NH*7;  }
    else           { A = g_hidR;   C = g_rfraw; N = NH*NR; }

    __shared__ float As[2][BK][BM];
    __shared__ float Bs[2][BK][BN];

    const int tid = threadIdx.x;
    const int tx  = tid & 15;
    const int ty  = tid >> 4;
    const int bn  = blockIdx.x;
    const int bm  = blockIdx.y;

    const float* Ag = A + bm*BM*KK;
    const float* Bg = B + bn*BN;

    float acc[8][4];
    #pragma unroll
    for (int i = 0; i < 8; i++)
        #pragma unroll
        for (int j = 0; j < 4; j++) acc[i][j] = 0.0f;

    float4 ra[4], rb[2];
    auto ldg_tile = [&](int k0){
        #pragma unroll
        for (int i = 0; i < 4; i++){
            int f = tid + i*256;
            int row = f >> 3, c4 = f & 7;
            ra[i] = *(const float4*)(Ag + row*KK + k0 + c4*4);
        }
        #pragma unroll
        for (int i = 0; i < 2; i++){
            int f = tid + i*256;
            int row = f >> 4, c4 = f & 15;
            rb[i] = *(const float4*)(Bg + (k0 + row)*N + c4*4);
        }
    };
    auto sts_tile = [&](int buf){
        #pragma unroll
        for (int i = 0; i < 4; i++){
            int f = tid + i*256;
            int row = f >> 3, c4 = f & 7;
            As[buf][c4*4+0][row] = ra[i].x;
            As[buf][c4*4+1][row] = ra[i].y;
            As[buf][c4*4+2][row] = ra[i].z;
            As[buf][c4*4+3][row] = ra[i].w;
        }
        #pragma unroll
        for (int i = 0; i < 2; i++){
            int f = tid + i*256;
            int row = f >> 4, c4 = f & 15;
            *(float4*)&Bs[buf][row][c4*4] = rb[i];
        }
    };

    ldg_tile(0);
    sts_tile(0);
    __syncthreads();

    const int KT = KK/BK;
    int buf = 0;
    for (int kt = 0; kt < KT; kt++){
        if (kt + 1 < KT) ldg_tile((kt+1)*BK);
        #pragma unroll
        for (int k = 0; k < BK; k++){
            float4 a0 = *(const float4*)&As[buf][k][ty*8];
            float4 a1 = *(const float4*)&As[buf][k][ty*8+4];
            float4 b0 = *(const float4*)&Bs[buf][k][tx*4];
            float a[8] = {a0.x,a0.y,a0.z,a0.w,a1.x,a1.y,a1.z,a1.w};
            float b[4] = {b0.x,b0.y,b0.z,b0.w};
            #pragma unroll
            for (int i = 0; i < 8; i++)
                #pragma unroll
                for (int j = 0; j < 4; j++)
                    acc[i][j] += a[i]*b[j];
        }
        if (kt + 1 < KT){
            sts_tile(buf^1);
            __syncthreads();
            buf ^= 1;
        }
    }

    #pragma unroll
    for (int i = 0; i < 8; i++){
        int gr = bm*BM + ty*8 + i;
        #pragma unroll
        for (int j = 0; j < 4; j++){
            int gc = bn*BN + tx*4 + j;
            C[gr*N + gc] = acc[i][j] + bias[gc];
        }
    }
}

// ============ mma.sync tf32 GEMM: g_hidden[93440,256] @ w2t^T, fused epi ====
// CTA tile 128x128x32, 8 warps (2m x 4n), warp tile 64x32, m16n8k8 tf32.
// smem rows padded to 36 floats so ldmatrix is bank-conflict-free.
#define TPAD 36
#define ABUF (128*TPAD*4)         // 18432 B per stage
#define OFF_SA 0
#define OFF_SB (2*ABUF)           // 36864
#define OFF_SBIAS (4*ABUF)        // 73728
#define SMEM_MMA (OFF_SBIAS + 512)

__global__ void __launch_bounds__(256) gemmMMA_kernel(const float* __restrict__ b2,
                                                      const float* __restrict__ x){
    extern __shared__ char smem[];
    const uint32_t sb = smem_u32(smem);
    float* sbias = (float*)(smem + OFF_SBIAS);

    const int tid  = threadIdx.x;
    const int lane = tid & 31;
    const int wid  = tid >> 5;
    const int wm   = wid >> 2;          // 0..1
    const int wn   = wid & 3;           // 0..3
    const int bn   = blockIdx.x;        // 0..5
    const int bm   = blockIdx.y;        // 0..729

    if (tid < 128) sbias[tid] = b2[bn*128 + tid];

    // cp.async task decomposition: 1024 16B-chunks per tile, 4 per thread
    const int lrow = tid >> 1;                    // for 128x(32 float) tiles: 2 chunks/row
    const float* Asrc = g_hidden + (size_t)(bm*128 + 0)*HID;
    const float* Bsrc = g_w2t    + (size_t)(bn*128 + 0)*HID;

    auto load_stage = [&](int kt, int st){
        uint32_t abase = sb + OFF_SA + st*ABUF;
        uint32_t bbase = sb + OFF_SB + st*ABUF;
        #pragma unroll
        for (int i = 0; i < 4; i++){
            int task = tid + i*256;               // 0..1023
            int row = task >> 3, q = task & 7;    // 8 chunks of 16B per 32-float row
            cpa16(abase + row*(TPAD*4) + q*16, Asrc + (size_t)row*HID + kt*32 + q*4);
        }
        #pragma unroll
        for (int i = 0; i < 4; i++){
            int task = tid + i*256;
            int row = task >> 3, q = task & 7;
            cpa16(bbase + row*(TPAD*4) + q*16, Bsrc + (size_t)row*HID + kt*32 + q*4);
        }
        CP_COMMIT();
    };

    float acc[4][4][4];
    #pragma unroll
    for (int i = 0; i < 4; i++)
        #pragma unroll
        for (int j = 0; j < 4; j++)
            #pragma unroll
            for (int k = 0; k < 4; k++) acc[i][j][k] = 0.0f;

    // ldmatrix per-lane offsets
    const int arow = (lane & 7) | (lane & 8);
    const int acol = (lane & 16) ? 4 : 0;
    const int brow = (lane & 7) | ((lane & 16) >> 1);
    const int bcol = (lane & 8) ? 4 : 0;
    const uint32_t a_l = (uint32_t)((wm*64 + arow)*(TPAD*4) + acol*4);
    const uint32_t b_l = (uint32_t)((wn*32 + brow)*(TPAD*4) + bcol*4);

    load_stage(0, 0);

    const int KT = 8;
    #pragma unroll 1
    for (int kt = 0; kt < KT; kt++){
        if (kt + 1 < KT){ load_stage(kt+1, (kt+1)&1); cpwait<1>(); }
        else cpwait<0>();
        __syncthreads();

        uint32_t abase = sb + OFF_SA + (kt&1)*ABUF + a_l;
        uint32_t bbase = sb + OFF_SB + (kt&1)*ABUF + b_l;
        #pragma unroll
        for (int ks = 0; ks < 4; ks++){
            uint32_t a0[4], a1[4], a2[4], a3[4];
            uint32_t bf[4][2];
            LDSM_X4(a0[0],a0[1],a0[2],a0[3], abase + 0*16*(TPAD*4) + ks*32);
            LDSM_X4(a1[0],a1[1],a1[2],a1[3], abase + 1*16*(TPAD*4) + ks*32);
            LDSM_X4(a2[0],a2[1],a2[2],a2[3], abase + 2*16*(TPAD*4) + ks*32);
            LDSM_X4(a3[0],a3[1],a3[2],a3[3], abase + 3*16*(TPAD*4) + ks*32);
            LDSM_X4(bf[0][0],bf[0][1],bf[1][0],bf[1][1], bbase + 0*16*(TPAD*4) + ks*32);
            LDSM_X4(bf[2][0],bf[2][1],bf[3][0],bf[3][1], bbase + 1*16*(TPAD*4) + ks*32);
            uint32_t (&af)[4][4] = *(uint32_t(*)[4][4])&a0[0];
            // af aliasing trick won't compile portably; do explicit:
            #define DO_MMA(mi, AR) \
                MMA_TF32(acc[mi][0][0],acc[mi][0][1],acc[mi][0][2],acc[mi][0][3], AR[0],AR[1],AR[2],AR[3], bf[0][0],bf[0][1]); \
                MMA_TF32(acc[mi][1][0],acc[mi][1][1],acc[mi][1][2],acc[mi][1][3], AR[0],AR[1],AR[2],AR[3], bf[1][0],bf[1][1]); \
                MMA_TF32(acc[mi][2][0],acc[mi][2][1],acc[mi][2][2],acc[mi][2][3], AR[0],AR[1],AR[2],AR[3], bf[2][0],bf[2][1]); \
                MMA_TF32(acc[mi][3][0],acc[mi][3][1],acc[mi][3][2],acc[mi][3][3], AR[0],AR[1],AR[2],AR[3], bf[3][0],bf[3][1])
            DO_MMA(0, a0);
            DO_MMA(1, a1);
            DO_MMA(2, a2);
            DO_MMA(3, a3);
            #undef DO_MMA
            (void)af;
        }
        __syncthreads();
    }

    // ---- fused epilogue: bias + activation -> Pl/Ev/Vm ----
    const int grp = bn >> 1;             // 0:Pl 1:Ev 2:Vm
    const int h0  = (bn & 1)*128;
    float* outp = (grp == 0) ? g_Pl : (grp == 1) ? g_Ev : g_Vm;
    const int qr = lane >> 2, qc = (lane & 3)*2;

    #pragma unroll
    for (int mi = 0; mi < 4; mi++){
        int r0 = bm*128 + wm*64 + mi*16 + qr;
        int r1 = r0 + 8;
        float s0 = 0.0f, s1 = 0.0f;
        if (grp == 0){ s0 = g_pfrac[r0]; s1 = g_pfrac[r1]; }
        if (grp == 1){ s0 = x[r0*6 + 1]; s1 = x[r1*6 + 1]; }
        #pragma unroll
        for (int ni = 0; ni < 4; ni++){
            int cl = wn*32 + ni*8 + qc;            // col within 128-block
            float b0v = sbias[cl], b1v = sbias[cl+1];
            float v0 = acc[mi][ni][0] + b0v;
            float v1 = acc[mi][ni][1] + b1v;
            float v2 = acc[mi][ni][2] + b0v;
            float v3 = acc[mi][ni][3] + b1v;
            float2 o0, o1;
            if (grp == 0){
                o0.x = s0*fminf(fmaxf(v0*(2.0f/6.0f)+0.5f,0.0f),1.0f);
                o0.y = s0*fminf(fmaxf(v1*(2.0f/6.0f)+0.5f,0.0f),1.0f);
                o1.x = s1*fminf(fmaxf(v2*(2.0f/6.0f)+0.5f,0.0f),1.0f);
                o1.y = s1*fminf(fmaxf(v3*(2.0f/6.0f)+0.5f,0.0f),1.0f);
            } else if (grp == 1){
                o0.x = s0*fmaxf(v0,0.0f)*2.0f;
                o0.y = s0*fmaxf(v1,0.0f)*2.0f;
                o1.x = s1*fmaxf(v2,0.0f)*2.0f;
                o1.y = s1*fmaxf(v3,0.0f)*2.0f;
            } else {
                o0.x = expf(v0); o0.y = expf(v1);
                o1.x = expf(v2); o1.y = expf(v3);
            }
            *(float2*)(outp + (size_t)r0*NH + h0 + cl) = o0;
            *(float2*)(outp + (size_t)r1*NH + h0 + cl) = o1;
        }
    }
}

// ---------------- kernel 5: fcW activations + ga softmax --------------------
__global__ void actW_kernel(){
    int s = blockIdx.x, h = threadIdx.x;
    const float* w = g_w + s*(NH*7);
    float kp = sigf(w[h]);
    float ks = sigf(w[NH+h]);
    float kg = sigf(w[2*NH+h])/10.0f;
    float gp = sigf(w[3*NH+h]);
    float e  = expf(w[4*NH+h]);
    float gL = e*e;
    float qb = fmaxf(w[5*NH+h], 0.0f);
    float gar = w[6*NH+h];

    __shared__ float red[8];
    float m = gar;
    #pragma unroll
    for (int o = 16; o; o >>= 1) m = fmaxf(m, __shfl_xor_sync(0xffffffffu, m, o));
    if ((h & 31) == 0) red[h>>5] = m;
    __syncthreads();
    if (h < 32){
        float v = (h < 8) ? red[h] : -1e30f;
        #pragma unroll
        for (int o = 4; o; o >>= 1) v = fmaxf(v, __shfl_xor_sync(0xffffffffu, v, o));
        if (h == 0) red[0] = v;
    }
    __syncthreads();
    float M = red[0];
    __syncthreads();
    float eg = expf(gar - M);
    float sm = eg;
    #pragma unroll
    for (int o = 16; o; o >>= 1) sm += __shfl_xor_sync(0xffffffffu, sm, o);
    if ((h & 31) == 0) red[h>>5] = sm;
    __syncthreads();
    if (h < 32){
        float v = (h < 8) ? red[h] : 0.0f;
        #pragma unroll
        for (int o = 4; o; o >>= 1) v += __shfl_xor_sync(0xffffffffu, v, o);
        if (h == 0) red[0] = v;
    }
    __syncthreads();
    float S = red[0];

    int ix = s*NH + h;
    g_kp[ix] = kp; g_ks[ix] = ks; g_kg[ix] = kg; g_gp[ix] = gp;
    g_gL[ix] = gL; g_qb[ix] = qb; g_ga[ix] = eg/S;
}

// ---------------- kernel 6: fcR relu + softmax over NR ----------------------
__global__ void actR_kernel(){
    int s = blockIdx.x, h = threadIdx.x;
    const float* rf = g_rfraw + s*(NH*NR) + h*NR;
    float v[NR];
    float m = -1e30f;
    #pragma unroll
    for (int j = 0; j < NR; j++){ v[j] = fmaxf(rf[j], 0.0f); m = fmaxf(m, v[j]); }
    float ssum = 0.0f;
    #pragma unroll
    for (int j = 0; j < NR; j++){ v[j] = expf(v[j]-m); ssum += v[j]; }
    float* out = g_r + s*(NH*NR) + h*NR;
    #pragma unroll
    for (int j = 0; j < NR; j++) out[j] = v[j]/ssum;
}

// ---------------- kernel 7: sequential reservoir scan -----------------------
__global__ void scan_kernel(){
    int s = blockIdx.x, h = threadIdx.x;
    int idx0 = s*NH + h;
    float kp = g_kp[idx0], ks = g_ks[idx0], kg = g_kg[idx0];
    float gp = g_gp[idx0], gL = g_gL[idx0], qb = g_qb[idx0];
    float Sf = 0.0f, Ss = 0.0f, Sg = 0.0f;

    int ix = idx0;
    float fl0 = g_Pl[ix], fev0 = g_Ev[ix], fm0 = g_Vm[ix];
    for (int t = 0; t < NT; t++){
        float fl = fl0, fev = fev0, fm = fm0;
        int ixc = ix;
        if (t + 1 < NT){
            ix += NS*NH;
            fl0 = g_Pl[ix]; fev0 = g_Ev[ix]; fm0 = g_Vm[ix];
        }
        float fs = g_Ps[t*NS + s];
        float a  = Sf + fs;
        float qf = fminf(a, fm);
        Sf = fmaxf(a - fm, 0.0f);
        float H  = fmaxf(Ss + fl + qf - fev, 0.0f);
        float qp = fmaxf(kp*(H - gL), 0.0f);
        float qsa = ks*fminf(H, gL);
        Ss = H - qp - qsa;
        float sgin = Sg + qsa*gp;
        float qg = kg*sgin + qb;
        Sg = (1.0f - kg)*sgin - qb;
        g_Q[ixc] = qp + qsa*(1.0f - gp) + qg;
    }
}

// ---------------- kernel 8: 16-tap conv + ga-weighted reduce ----------------
__global__ void conv_kernel(float* __restrict__ out){
    int s = blockIdx.x, h = threadIdx.x;
    float rr[NR];
    const float* rp = g_r + s*(NH*NR) + h*NR;
    #pragma unroll
    for (int j = 0; j < NR; j++) rr[j] = rp[j];
    float gah = g_ga[s*NH + h];
    int base = s*NH + h;

    float win[NR];
    #pragma unroll
    for (int j = 0; j < NR; j++) win[j] = g_Q[j*NS*NH + base];

    __shared__ float red[8];
    for (int tb = 0; tb < 352; tb += 16){
        #pragma unroll
        for (int tt = 0; tt < 16; tt++){
            int t = tb + tt;
            if (t < TOUT){
                float z = 0.0f;
                #pragma unroll
                for (int j = 0; j < NR; j++) z += rr[j]*win[(tt + j) & 15];
                float val = gah*z;
                #pragma unroll
                for (int o = 16; o; o >>= 1) val += __shfl_xor_sync(0xffffffffu, val, o);
                if ((h & 31) == 0) red[h>>5] = val;
                __syncthreads();
                if (h < 32){
                    float v = (h < 8) ? red[h] : 0.0f;
                    v += __shfl_xor_sync(0xffffffffu, v, 4);
                    v += __shfl_xor_sync(0xffffffffu, v, 2);
                    v += __shfl_xor_sync(0xffffffffu, v, 1);
                    if (h == 0) out[t*NS + s] = v;
                }
                __syncthreads();
                if (t + NR < NT) win[tt] = g_Q[(t + NR)*NS*NH + base];
            }
        }
    }
}

// ---------------- launch ----------------------------------------------------
extern "C" void kernel_launch(void* const* d_in, const int* in_sizes, int n_in,
                              void* d_out, int out_size){
    const float* x      = (const float*)d_in[0];
    const float* xc     = (const float*)d_in[1];
    const float* fcW_w1 = (const float*)d_in[2];
    const float* fcW_b1 = (const float*)d_in[3];
    const float* fcW_w2 = (const float*)d_in[4];
    const float* fcW_b2 = (const float*)d_in[5];
    const float* fcT_w1 = (const float*)d_in[6];
    const float* fcT_b1 = (const float*)d_in[7];
    const float* fcT_w2 = (const float*)d_in[8];
    const float* fcT_b2 = (const float*)d_in[9];
    const float* fcR_w1 = (const float*)d_in[10];
    const float* fcR_b1 = (const float*)d_in[11];
    const float* fcR_w2 = (const float*)d_in[12];
    const float* fcR_b2 = (const float*)d_in[13];
    float* out = (float*)d_out;

    cudaFuncSetAttribute(gemmMMA_kernel, cudaFuncAttributeMaxDynamicSharedMemorySize, SMEM_MMA);

    prep_kernel<<<(NTS + 255)/256, 256>>>(x);
    transposeB_kernel<<<dim3(768/32, 256/32), 256>>>(fcT_w2);
    layer1_kernel<<<dim3(NS, 3), 256>>>(xc, fcW_w1, fcW_b1, fcR_w1, fcR_b1, fcT_w1, fcT_b1);
    gemm_kernel<0><<<dim3((NH*7)/BN,  NS/BM),  256>>>(fcW_w2, fcW_b2);
    gemm_kernel<1><<<dim3((NH*NR)/BN, NS/BM),  256>>>(fcR_w2, fcR_b2);
    actW_kernel<<<NS, 256>>>();
    actR_kernel<<<NS, 256>>>();
    hiddenT_kernel<<<NTS, 256>>>(x, fcT_w1);
    gemmMMA_kernel<<<dim3(6, MTILES), 256, SMEM_MMA>>>(fcT_b2, x);
    scan_kernel<<<NS, 256>>>();
    conv_kernel<<<NS, 256>>>(out);
}

// round 4
// speedup vs baseline: 2.8203x; 1.4393x over previous
#include <cuda_runtime.h>
#include <cstdint>
#include <math.h>

#define NT  365
#define NS  256
#define NH  256
#define NG  32
#define NR  16
#define HID 256
#define NTS (NT*NS)          // 93440
#define TOUT (NT-NR+1)       // 350
#define MTILES 730           // 93440/128
#define QSTR 372             // padded time stride for transposed Q

// ---------------- scratch (device globals) ----------------------------------
__device__ float g_hidden[NTS*HID];
__device__ float g_Pl[NTS*NH];
__device__ float g_Ev[NTS*NH];
__device__ float g_Vm[NTS*NH];
__device__ float g_Qt[NS*NH*QSTR];    // time-contiguous Q
__device__ float g_hidW[NS*HID];
__device__ float g_hidR[NS*HID];
__device__ float g_baseT[NS*HID];
__device__ float g_w[NS*NH*7];
__device__ float g_rfraw[NS*NH*NR];
__device__ float g_kp[NS*NH], g_ks[NS*NH], g_kg[NS*NH], g_gp[NS*NH];
__device__ float g_gL[NS*NH], g_qb[NS*NH], g_ga[NS*NH];
__device__ float g_r[NS*NH*NR];
__device__ float g_PsT[NS*QSTR];      // snowfall, transposed [s][t]
__device__ float g_pfrac[NTS];
__device__ float g_w2t[768*HID];      // fcT_w2^T, tf32-rounded

__device__ __forceinline__ float sigf(float x){ return 1.0f/(1.0f+expf(-x)); }

__device__ __forceinline__ uint32_t smem_u32(const void* p){
    uint32_t a;
    asm("{ .reg .u64 t; cvta.to.shared.u64 t, %1; cvt.u32.u64 %0, t; }" : "=r"(a) : "l"(p));
    return a;
}
__device__ __forceinline__ float tf32r(float f){
    uint32_t u;
    asm("cvt.rna.tf32.f32 %0, %1;" : "=r"(u) : "f"(f));
    return __uint_as_float(u);
}
__device__ __forceinline__ void cpa16(uint32_t dst, const void* src){
    asm volatile("cp.async.cg.shared.global [%0], [%1], 16;" :: "r"(dst), "l"(src) : "memory");
}
#define CP_COMMIT() asm volatile("cp.async.commit_group;" ::: "memory")
template<int N> __device__ __forceinline__ void cpwait(){
    asm volatile("cp.async.wait_group %0;" :: "n"(N) : "memory");
}
#define LDSM_X4(r0,r1,r2,r3,addr) \
    asm volatile("ldmatrix.sync.aligned.m8n8.x4.shared.b16 {%0,%1,%2,%3}, [%4];" \
        : "=r"(r0),"=r"(r1),"=r"(r2),"=r"(r3) : "r"(addr))
#define MMA_TF32(c0,c1,c2,c3,a0,a1,a2,a3,b0,b1) \
    asm volatile("mma.sync.aligned.m16n8k8.row.col.f32.tf32.tf32.f32 " \
        "{%0,%1,%2,%3}, {%4,%5,%6,%7}, {%8,%9}, {%0,%1,%2,%3};" \
        : "+f"(c0),"+f"(c1),"+f"(c2),"+f"(c3) \
        : "r"(a0),"r"(a1),"r"(a2),"r"(a3), "r"(b0),"r"(b1))

// ============ setup: prep + transposeB + layer1 in one launch ================
__global__ void __launch_bounds__(256) setup_kernel(
        const float* __restrict__ x, const float* __restrict__ xc,
        const float* __restrict__ w2,
        const float* __restrict__ wW1, const float* __restrict__ bW1,
        const float* __restrict__ wR1, const float* __restrict__ bR1,
        const float* __restrict__ wT1, const float* __restrict__ bT1){
    __shared__ float sh[32*33];
    int bid = blockIdx.x, tid = threadIdx.x;
    if (bid < 365){
        int i = bid*256 + tid;
        float P  = x[i*6+0];
        float T1 = x[i*6+2];
        float T2 = x[i*6+3];
        float ratio = (T1+T2)/(T2-T1);
        ratio = fminf(fmaxf(ratio,-1.0f),1.0f);
        float vf = acosf(ratio)/3.1415f;
        if (T1 >= 0.0f) vf = 0.0f;
        if (T2 <= 0.0f) vf = 1.0f;
        int s = i & 255, t = i >> 8;
        g_PsT[s*QSTR + t] = P*vf;
        g_pfrac[i] = P*(1.0f-vf);
    } else if (bid < 365+192){
        int tb = bid - 365;
        int nb = (tb % 24)*32, kb = (tb / 24)*32;
        int tx = tid & 31, ty = tid >> 5;
        #pragma unroll
        for (int r = 0; r < 32; r += 8)
            sh[(ty+r)*33 + tx] = w2[(kb+ty+r)*768 + nb + tx];
        __syncthreads();
        #pragma unroll
        for (int r = 0; r < 32; r += 8)
            g_w2t[(nb+ty+r)*HID + kb + tx] = tf32r(sh[tx*33 + ty + r]);
    } else {
        int lb = bid - 557;
        int s = lb & 255, mode = lb >> 8, h = tid;
        float* xs = sh;
        if (h < NG) xs[h] = xc[s*NG + h];
        __syncthreads();
        const float* w; const float* b; float* out; bool dotanh;
        if (mode == 0){ w = wW1;      b = bW1; out = g_hidW;  dotanh = true;  }
        else if (mode == 1){ w = wR1; b = bR1; out = g_hidR;  dotanh = true;  }
        else { w = wT1 + 6*HID;       b = bT1; out = g_baseT; dotanh = false; }
        float acc = b[h];
        #pragma unroll
        for (int g = 0; g < NG; g++) acc += xs[g]*w[g*HID + h];
        out[s*HID + h] = dotanh ? tanhf(acc) : acc;
    }
}

// ---------------- fcT layer-1 per timestep (tf32-rounded) -------------------
__global__ void hiddenT_kernel(const float* __restrict__ x, const float* __restrict__ wT1){
    int row = blockIdx.x;
    int h   = threadIdx.x;
    int s   = row & (NS-1);
    __shared__ float xr[6];
    if (h < 6) xr[h] = x[row*6 + h];
    __syncthreads();
    float acc = g_baseT[s*HID + h];
    #pragma unroll
    for (int i = 0; i < 6; i++) acc += xr[i]*wT1[i*HID + h];
    g_hidden[row*HID + h] = tf32r(tanhf(acc));
}

// ---------------- combined small SIMT GEMMs (fcW + fcR layer 2) -------------
#define BM 128
#define BN 64
#define BK 32
#define KK 256

__global__ void __launch_bounds__(256) gemmWR_kernel(
        const float* __restrict__ Wb, const float* __restrict__ Wbias,
        const float* __restrict__ Rb, const float* __restrict__ Rbias){
    const float* A; float* C; const float* B; const float* bias; int N; int bn;
    if (blockIdx.x < 28){ A = g_hidW; C = g_w;     B = Wb; bias = Wbias; N = NH*7;  bn = blockIdx.x; }
    else                { A = g_hidR; C = g_rfraw; B = Rb; bias = Rbias; N = NH*NR; bn = blockIdx.x - 28; }

    __shared__ float As[2][BK][BM];
    __shared__ float Bs[2][BK][BN];

    const int tid = threadIdx.x;
    const int tx  = tid & 15;
    const int ty  = tid >> 4;
    const int bm  = blockIdx.y;

    const float* Ag = A + bm*BM*KK;
    const float* Bg = B + bn*BN;

    float acc[8][4];
    #pragma unroll
    for (int i = 0; i < 8; i++)
        #pragma unroll
        for (int j = 0; j < 4; j++) acc[i][j] = 0.0f;

    float4 ra[4], rb[2];
    auto ldg_tile = [&](int k0){
        #pragma unroll
        for (int i = 0; i < 4; i++){
            int f = tid + i*256;
            int row = f >> 3, c4 = f & 7;
            ra[i] = *(const float4*)(Ag + row*KK + k0 + c4*4);
        }
        #pragma unroll
        for (int i = 0; i < 2; i++){
            int f = tid + i*256;
            int row = f >> 4, c4 = f & 15;
            rb[i] = *(const float4*)(Bg + (k0 + row)*N + c4*4);
        }
    };
    auto sts_tile = [&](int buf){
        #pragma unroll
        for (int i = 0; i < 4; i++){
            int f = tid + i*256;
            int row = f >> 3, c4 = f & 7;
            As[buf][c4*4+0][row] = ra[i].x;
            As[buf][c4*4+1][row] = ra[i].y;
            As[buf][c4*4+2][row] = ra[i].z;
            As[buf][c4*4+3][row] = ra[i].w;
        }
        #pragma unroll
        for (int i = 0; i < 2; i++){
            int f = tid + i*256;
            int row = f >> 4, c4 = f & 15;
            *(float4*)&Bs[buf][row][c4*4] = rb[i];
        }
    };

    ldg_tile(0);
    sts_tile(0);
    __syncthreads();

    const int KT = KK/BK;
    int buf = 0;
    for (int kt = 0; kt < KT; kt++){
        if (kt + 1 < KT) ldg_tile((kt+1)*BK);
        #pragma unroll
        for (int k = 0; k < BK; k++){
            float4 a0 = *(const float4*)&As[buf][k][ty*8];
            float4 a1 = *(const float4*)&As[buf][k][ty*8+4];
            float4 b0 = *(const float4*)&Bs[buf][k][tx*4];
            float a[8] = {a0.x,a0.y,a0.z,a0.w,a1.x,a1.y,a1.z,a1.w};
            float b[4] = {b0.x,b0.y,b0.z,b0.w};
            #pragma unroll
            for (int i = 0; i < 8; i++)
                #pragma unroll
                for (int j = 0; j < 4; j++)
                    acc[i][j] += a[i]*b[j];
        }
        if (kt + 1 < KT){
            sts_tile(buf^1);
            __syncthreads();
            buf ^= 1;
        }
    }

    #pragma unroll
    for (int i = 0; i < 8; i++){
        int gr = bm*BM + ty*8 + i;
        #pragma unroll
        for (int j = 0; j < 4; j++){
            int gc = bn*BN + tx*4 + j;
            C[gr*N + gc] = acc[i][j] + bias[gc];
        }
    }
}

// ============ mma.sync tf32 GEMM, 4-stage cp.async, XOR swizzle =============
#define STG 16384
#define OFF_B4 (4*STG)            // 65536
#define OFF_SB2 (8*STG)           // 131072
#define SMEM_MMA (OFF_SB2 + 512)

__global__ void __launch_bounds__(256) gemmMMA_kernel(const float* __restrict__ b2,
                                                      const float* __restrict__ x){
    extern __shared__ char smem[];
    const uint32_t sb = smem_u32(smem);
    float* sbias = (float*)(smem + OFF_SB2);

    const int tid  = threadIdx.x;
    const int lane = tid & 31;
    const int wid  = tid >> 5;
    const int wm   = wid >> 2;
    const int wn   = wid & 3;
    const int bn   = blockIdx.x;        // 0..5
    const int bm   = blockIdx.y;        // 0..729

    if (tid < 128) sbias[tid] = b2[bn*128 + tid];

    const float* Asrc = g_hidden + (size_t)bm*128*HID;
    const float* Bsrc = g_w2t    + (size_t)bn*128*HID;

    auto load_stage = [&](int kt, int st){
        uint32_t ab = sb + st*STG;
        uint32_t bb = sb + OFF_B4 + st*STG;
        #pragma unroll
        for (int i = 0; i < 4; i++){
            int task = tid + i*256;
            int row = task >> 3, q = task & 7;
            uint32_t col = (uint32_t)(q*16) ^ (uint32_t)((row & 7) << 4);
            cpa16(ab + row*128 + col, Asrc + (size_t)row*HID + kt*32 + q*4);
        }
        #pragma unroll
        for (int i = 0; i < 4; i++){
            int task = tid + i*256;
            int row = task >> 3, q = task & 7;
            uint32_t col = (uint32_t)(q*16) ^ (uint32_t)((row & 7) << 4);
            cpa16(bb + row*128 + col, Bsrc + (size_t)row*HID + kt*32 + q*4);
        }
        CP_COMMIT();
    };

    float acc[4][4][4];
    #pragma unroll
    for (int i = 0; i < 4; i++)
        #pragma unroll
        for (int j = 0; j < 4; j++)
            #pragma unroll
            for (int k = 0; k < 4; k++) acc[i][j][k] = 0.0f;

    const int arow = (lane & 7) | (lane & 8);
    const uint32_t acb = (lane & 16) ? 16u : 0u;
    const int brow = (lane & 7) | ((lane & 16) >> 1);
    const uint32_t bcb = (lane & 8) ? 16u : 0u;
    const uint32_t aswz = (uint32_t)((arow & 7) << 4);
    const uint32_t bswz = (uint32_t)((brow & 7) << 4);
    uint32_t aoff[4], boff[2];
    #pragma unroll
    for (int mi = 0; mi < 4; mi++) aoff[mi] = (uint32_t)((wm*64 + mi*16 + arow)*128);
    #pragma unroll
    for (int p = 0; p < 2; p++)   boff[p]  = (uint32_t)((wn*32 + p*16 + brow)*128);

    load_stage(0, 0); load_stage(1, 1); load_stage(2, 2);

    #pragma unroll 1
    for (int kt = 0; kt < 8; kt++){
        if (kt < 6) cpwait<2>(); else if (kt == 6) cpwait<1>(); else cpwait<0>();
        __syncthreads();
        if (kt + 3 < 8) load_stage(kt+3, (kt+3)&3);

        uint32_t abase = sb + (kt&3)*STG;
        uint32_t bbase = sb + OFF_B4 + (kt&3)*STG;
        #pragma unroll
        for (int ks = 0; ks < 4; ks++){
            uint32_t acol = ((uint32_t)(acb + ks*32)) ^ aswz;
            uint32_t bcol = ((uint32_t)(bcb + ks*32)) ^ bswz;
            uint32_t a0[4], a1[4], a2[4], a3[4];
            uint32_t bf[4][2];
            LDSM_X4(a0[0],a0[1],a0[2],a0[3], abase + aoff[0] + acol);
            LDSM_X4(a1[0],a1[1],a1[2],a1[3], abase + aoff[1] + acol);
            LDSM_X4(a2[0],a2[1],a2[2],a2[3], abase + aoff[2] + acol);
            LDSM_X4(a3[0],a3[1],a3[2],a3[3], abase + aoff[3] + acol);
            LDSM_X4(bf[0][0],bf[0][1],bf[1][0],bf[1][1], bbase + boff[0] + bcol);
            LDSM_X4(bf[2][0],bf[2][1],bf[3][0],bf[3][1], bbase + boff[1] + bcol);
            #define DO_MMA(mi, AR) \
                MMA_TF32(acc[mi][0][0],acc[mi][0][1],acc[mi][0][2],acc[mi][0][3], AR[0],AR[1],AR[2],AR[3], bf[0][0],bf[0][1]); \
                MMA_TF32(acc[mi][1][0],acc[mi][1][1],acc[mi][1][2],acc[mi][1][3], AR[0],AR[1],AR[2],AR[3], bf[1][0],bf[1][1]); \
                MMA_TF32(acc[mi][2][0],acc[mi][2][1],acc[mi][2][2],acc[mi][2][3], AR[0],AR[1],AR[2],AR[3], bf[2][0],bf[2][1]); \
                MMA_TF32(acc[mi][3][0],acc[mi][3][1],acc[mi][3][2],acc[mi][3][3], AR[0],AR[1],AR[2],AR[3], bf[3][0],bf[3][1])
            DO_MMA(0, a0);
            DO_MMA(1, a1);
            DO_MMA(2, a2);
            DO_MMA(3, a3);
            #undef DO_MMA
        }
    }

    // ---- fused epilogue: bias + activation -> Pl/Ev/Vm ----
    const int grp = bn >> 1;
    const int h0  = (bn & 1)*128;
    float* outp = (grp == 0) ? g_Pl : (grp == 1) ? g_Ev : g_Vm;
    const int qr = lane >> 2, qc = (lane & 3)*2;

    #pragma unroll
    for (int mi = 0; mi < 4; mi++){
        int r0 = bm*128 + wm*64 + mi*16 + qr;
        int r1 = r0 + 8;
        float s0 = 0.0f, s1 = 0.0f;
        if (grp == 0){ s0 = g_pfrac[r0]; s1 = g_pfrac[r1]; }
        if (grp == 1){ s0 = x[r0*6 + 1]; s1 = x[r1*6 + 1]; }
        #pragma unroll
        for (int ni = 0; ni < 4; ni++){
            int cl = wn*32 + ni*8 + qc;
            float b0v = sbias[cl], b1v = sbias[cl+1];
            float v0 = acc[mi][ni][0] + b0v;
            float v1 = acc[mi][ni][1] + b1v;
            float v2 = acc[mi][ni][2] + b0v;
            float v3 = acc[mi][ni][3] + b1v;
            float2 o0, o1;
            if (grp == 0){
                o0.x = s0*fminf(fmaxf(v0*(2.0f/6.0f)+0.5f,0.0f),1.0f);
                o0.y = s0*fminf(fmaxf(v1*(2.0f/6.0f)+0.5f,0.0f),1.0f);
                o1.x = s1*fminf(fmaxf(v2*(2.0f/6.0f)+0.5f,0.0f),1.0f);
                o1.y = s1*fminf(fmaxf(v3*(2.0f/6.0f)+0.5f,0.0f),1.0f);
            } else if (grp == 1){
                o0.x = s0*fmaxf(v0,0.0f)*2.0f;
                o0.y = s0*fmaxf(v1,0.0f)*2.0f;
                o1.x = s1*fmaxf(v2,0.0f)*2.0f;
                o1.y = s1*fmaxf(v3,0.0f)*2.0f;
            } else {
                o0.x = expf(v0); o0.y = expf(v1);
                o1.x = expf(v2); o1.y = expf(v3);
            }
            *(float2*)(outp + (size_t)r0*NH + h0 + cl) = o0;
            *(float2*)(outp + (size_t)r1*NH + h0 + cl) = o1;
        }
    }
}

// ---------------- fcW + fcR activations, one launch --------------------------
__global__ void __launch_bounds__(256) actWR_kernel(){
    int h = threadIdx.x;
    if (blockIdx.x < NS){
        int s = blockIdx.x;
        const float* w = g_w + s*(NH*7);
        float kp = sigf(w[h]);
        float ks = sigf(w[NH+h]);
        float kg = sigf(w[2*NH+h])/10.0f;
        float gp = sigf(w[3*NH+h]);
        float e  = expf(w[4*NH+h]);
        float gL = e*e;
        float qb = fmaxf(w[5*NH+h], 0.0f);
        float gar = w[6*NH+h];

        __shared__ float red[8];
        float m = gar;
        #pragma unroll
        for (int o = 16; o; o >>= 1) m = fmaxf(m, __shfl_xor_sync(0xffffffffu, m, o));
        if ((h & 31) == 0) red[h>>5] = m;
        __syncthreads();
        if (h < 32){
            float v = (h < 8) ? red[h] : -1e30f;
            #pragma unroll
            for (int o = 4; o; o >>= 1) v = fmaxf(v, __shfl_xor_sync(0xffffffffu, v, o));
            if (h == 0) red[0] = v;
        }
        __syncthreads();
        float M = red[0];
        __syncthreads();
        float eg = expf(gar - M);
        float sm = eg;
        #pragma unroll
        for (int o = 16; o; o >>= 1) sm += __shfl_xor_sync(0xffffffffu, sm, o);
        if ((h & 31) == 0) red[h>>5] = sm;
        __syncthreads();
        if (h < 32){
            float v = (h < 8) ? red[h] : 0.0f;
            #pragma unroll
            for (int o = 4; o; o >>= 1) v += __shfl_xor_sync(0xffffffffu, v, o);
            if (h == 0) red[0] = v;
        }
        __syncthreads();
        float S = red[0];

        int ix = s*NH + h;
        g_kp[ix] = kp; g_ks[ix] = ks; g_kg[ix] = kg; g_gp[ix] = gp;
        g_gL[ix] = gL; g_qb[ix] = qb; g_ga[ix] = eg/S;
    } else {
        int s = blockIdx.x - NS;
        const float* rf = g_rfraw + s*(NH*NR) + h*NR;
        float v[NR];
        float m = -1e30f;
        #pragma unroll
        for (int j = 0; j < NR; j++){ v[j] = fmaxf(rf[j], 0.0f); m = fmaxf(m, v[j]); }
        float ssum = 0.0f;
        #pragma unroll
        for (int j = 0; j < NR; j++){ v[j] = expf(v[j]-m); ssum += v[j]; }
        float* out = g_r + s*(NH*NR) + h*NR;
        #pragma unroll
        for (int j = 0; j < NR; j++) out[j] = v[j]/ssum;
    }
}

// ============ fused reservoir scan (PF8, transposed Q) + 16-tap conv ========
__global__ void __launch_bounds__(256) scanconv_kernel(float* __restrict__ out){
    __shared__ float sPs[368];
    __shared__ float sQ[256*33];       // reused as yPart in phase B

    const int s = blockIdx.x, tid = threadIdx.x, h = tid;

    for (int i = tid; i < NT; i += 256) sPs[i] = g_PsT[s*QSTR + i];

    const int idx0 = (s << 8) + h;
    const float kp = g_kp[idx0], ks = g_ks[idx0], kg = g_kg[idx0];
    const float gp = g_gp[idx0], gL = g_gL[idx0], qb = g_qb[idx0];
    __syncthreads();

    float Sf = 0.0f, Ss = 0.0f, Sg = 0.0f;
    const size_t str = (size_t)NS*NH;
    float fl[8], fev[8], fm[8];
    {
        size_t ix = idx0;
        #pragma unroll
        for (int i = 0; i < 8; i++){
            fl[i] = g_Pl[ix]; fev[i] = g_Ev[ix]; fm[i] = g_Vm[ix];
            ix += str;
        }
    }
    size_t ixn = (size_t)idx0 + 8*str;
    float* qrow = g_Qt + (size_t)idx0*QSTR;

    auto step = [&](int tt, float cfl, float cfev, float cfm){
        float fs = sPs[tt];
        float a  = Sf + fs;
        float qf = fminf(a, cfm);
        Sf = fmaxf(a - cfm, 0.0f);
        float H  = fmaxf(Ss + cfl + qf - cfev, 0.0f);
        float qp = fmaxf(kp*(H - gL), 0.0f);
        float qsa = ks*fminf(H, gL);
        Ss = H - qp - qsa;
        float sgin = Sg + qsa*gp;
        float qg = kg*sgin + qb;
        Sg = (1.0f - kg)*sgin - qb;
        return qp + qsa*(1.0f - gp) + qg;
    };
    auto flush = [&](int t0, int cnt){
        __syncthreads();
        #pragma unroll
        for (int it = 0; it < 32; it++){
            int u = tid + it*256;
            int hh = u >> 5, tt = u & 31;
            if (tt < cnt)
                g_Qt[(size_t)((s<<8)+hh)*QSTR + t0 + tt] = sQ[hh*33 + tt];
        }
        __syncthreads();
    };

    #pragma unroll 1
    for (int tb = 0; tb < 360; tb += 8){
        #pragma unroll
        for (int i = 0; i < 8; i++){
            int tt = tb + i;
            float cfl = fl[i], cfev = fev[i], cfm = fm[i];
            if (tt + 8 < NT){
                fl[i] = g_Pl[ixn]; fev[i] = g_Ev[ixn]; fm[i] = g_Vm[ixn];
                ixn += str;
            }
            float q = step(tt, cfl, cfev, cfm);
            sQ[h*33 + (tt & 31)] = q;
            if ((tt & 31) == 31) flush(tt - 31, 32);
        }
    }
    #pragma unroll
    for (int i = 0; i < 5; i++){
        int tt = 360 + i;
        float q = step(tt, fl[i], fev[i], fm[i]);
        sQ[h*33 + (tt & 31)] = q;
    }
    flush(352, 13);
    (void)qrow;

    // ---- phase B: conv + ga-weighted reduce over h ----
    const int w = tid >> 5, lane = tid & 31;
    const int t0 = lane*11;
    float y[11];
    #pragma unroll
    for (int i = 0; i < 11; i++) y[i] = 0.0f;

    for (int hh = 0; hh < 32; hh++){
        int base = (s << 8) + w*32 + hh;
        float gah = g_ga[base];
        const float* rp = g_r + (size_t)base*NR;
        float c[16];
        #pragma unroll
        for (int j = 0; j < 16; j++) c[j] = gah*rp[j];
        const float* qp2 = g_Qt + (size_t)base*QSTR + t0;
        float q[26];
        #pragma unroll
        for (int u = 0; u < 26; u++) q[u] = (t0 + u < NT) ? qp2[u] : 0.0f;
        #pragma unroll
        for (int i = 0; i < 11; i++){
            float acc = y[i];
            #pragma unroll
            for (int j = 0; j < 16; j++) acc += c[j]*q[i+j];
            y[i] = acc;
        }
    }
    float* yP = sQ;
    #pragma unroll
    for (int i = 0; i < 11; i++) yP[w*352 + t0 + i] = y[i];
    __syncthreads();
    for (int t = tid; t < TOUT; t += 256){
        float acc = 0.0f;
        #pragma unroll
        for (int w2 = 0; w2 < 8; w2++) acc += yP[w2*352 + t];
        out[t*NS + s] = acc;
    }
}

// ---------------- launch ----------------------------------------------------
extern "C" void kernel_launch(void* const* d_in, const int* in_sizes, int n_in,
                              void* d_out, int out_size){
    const float* x      = (const float*)d_in[0];
    const float* xc     = (const float*)d_in[1];
    const float* fcW_w1 = (const float*)d_in[2];
    const float* fcW_b1 = (const float*)d_in[3];
    const float* fcW_w2 = (const float*)d_in[4];
    const float* fcW_b2 = (const float*)d_in[5];
    const float* fcT_w1 = (const float*)d_in[6];
    const float* fcT_b1 = (const float*)d_in[7];
    const float* fcT_w2 = (const float*)d_in[8];
    const float* fcT_b2 = (const float*)d_in[9];
    const float* fcR_w1 = (const float*)d_in[10];
    const float* fcR_b1 = (const float*)d_in[11];
    const float* fcR_w2 = (const float*)d_in[12];
    const float* fcR_b2 = (const float*)d_in[13];
    float* out = (float*)d_out;

    cudaFuncSetAttribute(gemmMMA_kernel, cudaFuncAttributeMaxDynamicSharedMemorySize, SMEM_MMA);

    setup_kernel<<<365+192+768, 256>>>(x, xc, fcT_w2, fcW_w1, fcW_b1, fcR_w1, fcR_b1, fcT_w1, fcT_b1);
    gemmWR_kernel<<<dim3(92, 2), 256>>>(fcW_w2, fcW_b2, fcR_w2, fcR_b2);
    actWR_kernel<<<2*NS, 256>>>();
    hiddenT_kernel<<<NTS, 256>>>(x, fcT_w1);
    gemmMMA_kernel<<<dim3(6, MTILES), 256, SMEM_MMA>>>(fcT_b2, x);
    scanconv_kernel<<<NS, 256>>>(out);
}

// round 5
// speedup vs baseline: 3.9586x; 1.4036x over previous
#include <cuda_runtime.h>
#include <cuda_fp16.h>
#include <cstdint>
#include <math.h>

#define NT  365
#define NS  256
#define NH  256
#define NG  32
#define NR  16
#define HID 256
#define NTS (NT*NS)          // 93440
#define TOUT (NT-NR+1)       // 350
#define MTILES 730           // 93440/128
#define QSTR 372             // padded time stride for transposed Q

// ---------------- scratch (device globals) ----------------------------------
__device__ __half g_hiddenH[NTS*HID]; // fcT layer-1 output (tanh, fp16)
__device__ float g_Pl[NTS*NH];
__device__ float g_Ev[NTS*NH];
__device__ float g_Vm[NTS*NH];
__device__ float g_Qt[NS*NH*QSTR];    // time-contiguous Q
__device__ float g_hidW[NS*HID];
__device__ float g_hidR[NS*HID];
__device__ float g_baseT[NS*HID];
__device__ float g_w[NS*NH*7];
__device__ float g_rfraw[NS*NH*NR];
__device__ float g_kp[NS*NH], g_ks[NS*NH], g_kg[NS*NH], g_gp[NS*NH];
__device__ float g_gL[NS*NH], g_qb[NS*NH], g_ga[NS*NH];
__device__ float g_r[NS*NH*NR];
__device__ float g_PsT[NS*QSTR];      // snowfall, transposed [s][t]
__device__ float g_pfrac[NTS];
__device__ __half g_w2tH[768*HID];    // fcT_w2^T, fp16

__device__ __forceinline__ float sigf(float x){ return 1.0f/(1.0f+expf(-x)); }

__device__ __forceinline__ uint32_t smem_u32(const void* p){
    uint32_t a;
    asm("{ .reg .u64 t; cvta.to.shared.u64 t, %1; cvt.u32.u64 %0, t; }" : "=r"(a) : "l"(p));
    return a;
}
__device__ __forceinline__ void cpa16(uint32_t dst, const void* src){
    asm volatile("cp.async.cg.shared.global [%0], [%1], 16;" :: "r"(dst), "l"(src) : "memory");
}
#define CP_COMMIT() asm volatile("cp.async.commit_group;" ::: "memory")
template<int N> __device__ __forceinline__ void cpwait(){
    asm volatile("cp.async.wait_group %0;" :: "n"(N) : "memory");
}
#define LDSM_X4(r0,r1,r2,r3,addr) \
    asm volatile("ldmatrix.sync.aligned.m8n8.x4.shared.b16 {%0,%1,%2,%3}, [%4];" \
        : "=r"(r0),"=r"(r1),"=r"(r2),"=r"(r3) : "r"(addr))
#define MMA_F16(c0,c1,c2,c3,a0,a1,a2,a3,b0,b1) \
    asm volatile("mma.sync.aligned.m16n8k16.row.col.f32.f16.f16.f32 " \
        "{%0,%1,%2,%3}, {%4,%5,%6,%7}, {%8,%9}, {%0,%1,%2,%3};" \
        : "+f"(c0),"+f"(c1),"+f"(c2),"+f"(c3) \
        : "r"(a0),"r"(a1),"r"(a2),"r"(a3), "r"(b0),"r"(b1))

// ============ setup: prep + transposeB(fp16) + layer1 in one launch =========
__global__ void __launch_bounds__(256) setup_kernel(
        const float* __restrict__ x, const float* __restrict__ xc,
        const float* __restrict__ w2,
        const float* __restrict__ wW1, const float* __restrict__ bW1,
        const float* __restrict__ wR1, const float* __restrict__ bR1,
        const float* __restrict__ wT1, const float* __restrict__ bT1){
    __shared__ float sh[32*33];
    int bid = blockIdx.x, tid = threadIdx.x;
    if (bid < 365){
        int i = bid*256 + tid;
        float P  = x[i*6+0];
        float T1 = x[i*6+2];
        float T2 = x[i*6+3];
        float ratio = (T1+T2)/(T2-T1);
        ratio = fminf(fmaxf(ratio,-1.0f),1.0f);
        float vf = acosf(ratio)/3.1415f;
        if (T1 >= 0.0f) vf = 0.0f;
        if (T2 <= 0.0f) vf = 1.0f;
        int s = i & 255, t = i >> 8;
        g_PsT[s*QSTR + t] = P*vf;
        g_pfrac[i] = P*(1.0f-vf);
    } else if (bid < 365+192){
        int tb = bid - 365;
        int nb = (tb % 24)*32, kb = (tb / 24)*32;
        int tx = tid & 31, ty = tid >> 5;
        #pragma unroll
        for (int r = 0; r < 32; r += 8)
            sh[(ty+r)*33 + tx] = w2[(kb+ty+r)*768 + nb + tx];
        __syncthreads();
        #pragma unroll
        for (int r = 0; r < 32; r += 8)
            g_w2tH[(nb+ty+r)*HID + kb + tx] = __float2half(sh[tx*33 + ty + r]);
    } else {
        int lb = bid - 557;
        int s = lb & 255, mode = lb >> 8, h = tid;
        float* xs = sh;
        if (h < NG) xs[h] = xc[s*NG + h];
        __syncthreads();
        const float* w; const float* b; float* out; bool dotanh;
        if (mode == 0){ w = wW1;      b = bW1; out = g_hidW;  dotanh = true;  }
        else if (mode == 1){ w = wR1; b = bR1; out = g_hidR;  dotanh = true;  }
        else { w = wT1 + 6*HID;       b = bT1; out = g_baseT; dotanh = false; }
        float acc = b[h];
        #pragma unroll
        for (int g = 0; g < NG; g++) acc += xs[g]*w[g*HID + h];
        out[s*HID + h] = dotanh ? tanhf(acc) : acc;
    }
}

// ---------------- fcT layer-1 per timestep (fp16 out) ------------------------
__global__ void __launch_bounds__(256) hiddenT_kernel(const float* __restrict__ x,
                                                      const float* __restrict__ wT1){
    int sub = threadIdx.x >> 7;
    int row = blockIdx.x*2 + sub;
    int hl  = threadIdx.x & 127;
    int hh  = hl*2;
    int s   = row & (NS-1);
    __shared__ float xr[2][6];
    if (hl < 6) xr[sub][hl] = x[row*6 + hl];
    __syncthreads();
    float a0 = g_baseT[s*HID + hh];
    float a1 = g_baseT[s*HID + hh + 1];
    #pragma unroll
    for (int i = 0; i < 6; i++){
        float f = xr[sub][i];
        a0 += f*wT1[i*HID + hh];
        a1 += f*wT1[i*HID + hh + 1];
    }
    *(half2*)(g_hiddenH + (size_t)row*HID + hh) = __floats2half2_rn(tanhf(a0), tanhf(a1));
}

// ---------------- combined small SIMT GEMMs (fcW + fcR layer 2) -------------
#define BM 128
#define BN 64
#define BK 32
#define KK 256

__global__ void __launch_bounds__(256) gemmWR_kernel(
        const float* __restrict__ Wb, const float* __restrict__ Wbias,
        const float* __restrict__ Rb, const float* __restrict__ Rbias){
    const float* A; float* C; const float* B; const float* bias; int N; int bn;
    if (blockIdx.x < 28){ A = g_hidW; C = g_w;     B = Wb; bias = Wbias; N = NH*7;  bn = blockIdx.x; }
    else                { A = g_hidR; C = g_rfraw; B = Rb; bias = Rbias; N = NH*NR; bn = blockIdx.x - 28; }

    __shared__ float As[2][BK][BM];
    __shared__ float Bs[2][BK][BN];

    const int tid = threadIdx.x;
    const int tx  = tid & 15;
    const int ty  = tid >> 4;
    const int bm  = blockIdx.y;

    const float* Ag = A + bm*BM*KK;
    const float* Bg = B + bn*BN;

    float acc[8][4];
    #pragma unroll
    for (int i = 0; i < 8; i++)
        #pragma unroll
        for (int j = 0; j < 4; j++) acc[i][j] = 0.0f;

    float4 ra[4], rb[2];
    auto ldg_tile = [&](int k0){
        #pragma unroll
        for (int i = 0; i < 4; i++){
            int f = tid + i*256;
            int row = f >> 3, c4 = f & 7;
            ra[i] = *(const float4*)(Ag + row*KK + k0 + c4*4);
        }
        #pragma unroll
        for (int i = 0; i < 2; i++){
            int f = tid + i*256;
            int row = f >> 4, c4 = f & 15;
            rb[i] = *(const float4*)(Bg + (k0 + row)*N + c4*4);
        }
    };
    auto sts_tile = [&](int buf){
        #pragma unroll
        for (int i = 0; i < 4; i++){
            int f = tid + i*256;
            int row = f >> 3, c4 = f & 7;
            As[buf][c4*4+0][row] = ra[i].x;
            As[buf][c4*4+1][row] = ra[i].y;
            As[buf][c4*4+2][row] = ra[i].z;
            As[buf][c4*4+3][row] = ra[i].w;
        }
        #pragma unroll
        for (int i = 0; i < 2; i++){
            int f = tid + i*256;
            int row = f >> 4, c4 = f & 15;
            *(float4*)&Bs[buf][row][c4*4] = rb[i];
        }
    };

    ldg_tile(0);
    sts_tile(0);
    __syncthreads();

    const int KT = KK/BK;
    int buf = 0;
    for (int kt = 0; kt < KT; kt++){
        if (kt + 1 < KT) ldg_tile((kt+1)*BK);
        #pragma unroll
        for (int k = 0; k < BK; k++){
            float4 a0 = *(const float4*)&As[buf][k][ty*8];
            float4 a1 = *(const float4*)&As[buf][k][ty*8+4];
            float4 b0 = *(const float4*)&Bs[buf][k][tx*4];
            float a[8] = {a0.x,a0.y,a0.z,a0.w,a1.x,a1.y,a1.z,a1.w};
            float b[4] = {b0.x,b0.y,b0.z,b0.w};
            #pragma unroll
            for (int i = 0; i < 8; i++)
                #pragma unroll
                for (int j = 0; j < 4; j++)
                    acc[i][j] += a[i]*b[j];
        }
        if (kt + 1 < KT){
            sts_tile(buf^1);
            __syncthreads();
            buf ^= 1;
        }
    }

    #pragma unroll
    for (int i = 0; i < 8; i++){
        int gr = bm*BM + ty*8 + i;
        #pragma unroll
        for (int j = 0; j < 4; j++){
            int gc = bn*BN + tx*4 + j;
            C[gr*N + gc] = acc[i][j] + bias[gc];
        }
    }
}

// ============ fp16 mma.sync GEMM, 4-stage cp.async, XOR swizzle =============
// CTA 128x128x(K=256, chunk 32). A/B smem rows = 64B (32 halves).
#define STG16 8192
#define OFF_BH (4*STG16)          // 32768
#define OFF_SB2 (8*STG16)         // 65536
#define SMEM_MMA (OFF_SB2 + 512)

__global__ void __launch_bounds__(256) gemmMMA_kernel(const float* __restrict__ b2,
                                                      const float* __restrict__ x){
    extern __shared__ char smem[];
    const uint32_t sb = smem_u32(smem);
    float* sbias = (float*)(smem + OFF_SB2);

    const int tid  = threadIdx.x;
    const int lane = tid & 31;
    const int wid  = tid >> 5;
    const int wm   = wid >> 2;
    const int wn   = wid & 3;
    const int bn   = blockIdx.x;        // 0..5
    const int bm   = blockIdx.y;        // 0..729

    if (tid < 128) sbias[tid] = b2[bn*128 + tid];

    const __half* Asrc = g_hiddenH + (size_t)bm*128*HID;
    const __half* Bsrc = g_w2tH    + (size_t)bn*128*HID;

    auto load_stage = [&](int kt, int st){
        uint32_t ab = sb + st*STG16;
        uint32_t bb = sb + OFF_BH + st*STG16;
        #pragma unroll
        for (int i = 0; i < 2; i++){
            int task = tid + i*256;
            int row = task >> 2, q = task & 3;
            uint32_t col = (uint32_t)(q*16) ^ (uint32_t)(((row>>1)&3)<<4);
            cpa16(ab + row*64 + col, Asrc + (size_t)row*HID + kt*32 + q*8);
        }
        #pragma unroll
        for (int i = 0; i < 2; i++){
            int task = tid + i*256;
            int row = task >> 2, q = task & 3;
            uint32_t col = (uint32_t)(q*16) ^ (uint32_t)(((row>>1)&3)<<4);
            cpa16(bb + row*64 + col, Bsrc + (size_t)row*HID + kt*32 + q*8);
        }
        CP_COMMIT();
    };

    float acc[4][4][4];
    #pragma unroll
    for (int i = 0; i < 4; i++)
        #pragma unroll
        for (int j = 0; j < 4; j++)
            #pragma unroll
            for (int k = 0; k < 4; k++) acc[i][j][k] = 0.0f;

    // ldmatrix lane mappings
    const int arow = lane & 15;
    const uint32_t acb = (lane & 16) ? 16u : 0u;
    const uint32_t aswz = (uint32_t)(((arow>>1)&3)<<4);
    const int brow = (lane & 7) | ((lane & 16) >> 1);
    const uint32_t bcb = (lane & 8) ? 16u : 0u;
    const uint32_t bswz = (uint32_t)(((brow>>1)&3)<<4);
    uint32_t aoff[4], boff[2];
    #pragma unroll
    for (int mi = 0; mi < 4; mi++) aoff[mi] = (uint32_t)((wm*64 + mi*16 + arow)*64);
    #pragma unroll
    for (int p = 0; p < 2; p++)   boff[p]  = (uint32_t)((wn*32 + p*16 + brow)*64);

    load_stage(0, 0); load_stage(1, 1); load_stage(2, 2);

    #pragma unroll 1
    for (int kt = 0; kt < 8; kt++){
        if (kt < 6) cpwait<2>(); else if (kt == 6) cpwait<1>(); else cpwait<0>();
        __syncthreads();
        if (kt + 3 < 8) load_stage(kt+3, (kt+3)&3);

        uint32_t abase = sb + (kt&3)*STG16;
        uint32_t bbase = sb + OFF_BH + (kt&3)*STG16;
        #pragma unroll
        for (int ks = 0; ks < 2; ks++){
            uint32_t acol = (acb + (uint32_t)(ks*32)) ^ aswz;
            uint32_t bcol = (bcb + (uint32_t)(ks*32)) ^ bswz;
            uint32_t aF[4][4];
            uint32_t bF[4][2];
            LDSM_X4(aF[0][0],aF[0][1],aF[0][2],aF[0][3], abase + aoff[0] + acol);
            LDSM_X4(aF[1][0],aF[1][1],aF[1][2],aF[1][3], abase + aoff[1] + acol);
            LDSM_X4(aF[2][0],aF[2][1],aF[2][2],aF[2][3], abase + aoff[2] + acol);
            LDSM_X4(aF[3][0],aF[3][1],aF[3][2],aF[3][3], abase + aoff[3] + acol);
            LDSM_X4(bF[0][0],bF[0][1],bF[1][0],bF[1][1], bbase + boff[0] + bcol);
            LDSM_X4(bF[2][0],bF[2][1],bF[3][0],bF[3][1], bbase + boff[1] + bcol);
            #pragma unroll
            for (int mi = 0; mi < 4; mi++)
                #pragma unroll
                for (int ni = 0; ni < 4; ni++)
                    MMA_F16(acc[mi][ni][0],acc[mi][ni][1],acc[mi][ni][2],acc[mi][ni][3],
                            aF[mi][0],aF[mi][1],aF[mi][2],aF[mi][3],
                            bF[ni][0],bF[ni][1]);
        }
    }

    // ---- fused epilogue: bias + activation -> Pl/Ev/Vm ----
    const int grp = bn >> 1;
    const int h0  = (bn & 1)*128;
    float* outp = (grp == 0) ? g_Pl : (grp == 1) ? g_Ev : g_Vm;
    const int qr = lane >> 2, qc = (lane & 3)*2;

    #pragma unroll
    for (int mi = 0; mi < 4; mi++){
        int r0 = bm*128 + wm*64 + mi*16 + qr;
        int r1 = r0 + 8;
        float s0 = 0.0f, s1 = 0.0f;
        if (grp == 0){ s0 = g_pfrac[r0]; s1 = g_pfrac[r1]; }
        if (grp == 1){ s0 = x[r0*6 + 1]; s1 = x[r1*6 + 1]; }
        #pragma unroll
        for (int ni = 0; ni < 4; ni++){
            int cl = wn*32 + ni*8 + qc;
            float b0v = sbias[cl], b1v = sbias[cl+1];
            float v0 = acc[mi][ni][0] + b0v;
            float v1 = acc[mi][ni][1] + b1v;
            float v2 = acc[mi][ni][2] + b0v;
            float v3 = acc[mi][ni][3] + b1v;
            float2 o0, o1;
            if (grp == 0){
                o0.x = s0*fminf(fmaxf(v0*(2.0f/6.0f)+0.5f,0.0f),1.0f);
                o0.y = s0*fminf(fmaxf(v1*(2.0f/6.0f)+0.5f,0.0f),1.0f);
                o1.x = s1*fminf(fmaxf(v2*(2.0f/6.0f)+0.5f,0.0f),1.0f);
                o1.y = s1*fminf(fmaxf(v3*(2.0f/6.0f)+0.5f,0.0f),1.0f);
            } else if (grp == 1){
                o0.x = s0*fmaxf(v0,0.0f)*2.0f;
                o0.y = s0*fmaxf(v1,0.0f)*2.0f;
                o1.x = s1*fmaxf(v2,0.0f)*2.0f;
                o1.y = s1*fmaxf(v3,0.0f)*2.0f;
            } else {
                o0.x = expf(v0); o0.y = expf(v1);
                o1.x = expf(v2); o1.y = expf(v3);
            }
            *(float2*)(outp + (size_t)r0*NH + h0 + cl) = o0;
            *(float2*)(outp + (size_t)r1*NH + h0 + cl) = o1;
        }
    }
}

// ---------------- fcW + fcR activations, one launch --------------------------
__global__ void __launch_bounds__(256) actWR_kernel(){
    int h = threadIdx.x;
    if (blockIdx.x < NS){
        int s = blockIdx.x;
        const float* w = g_w + s*(NH*7);
        float kp = sigf(w[h]);
        float ks = sigf(w[NH+h]);
        float kg = sigf(w[2*NH+h])/10.0f;
        float gp = sigf(w[3*NH+h]);
        float e  = expf(w[4*NH+h]);
        float gL = e*e;
        float qb = fmaxf(w[5*NH+h], 0.0f);
        float gar = w[6*NH+h];

        __shared__ float red[8];
        float m = gar;
        #pragma unroll
        for (int o = 16; o; o >>= 1) m = fmaxf(m, __shfl_xor_sync(0xffffffffu, m, o));
        if ((h & 31) == 0) red[h>>5] = m;
        __syncthreads();
        if (h < 32){
            float v = (h < 8) ? red[h] : -1e30f;
            #pragma unroll
            for (int o = 4; o; o >>= 1) v = fmaxf(v, __shfl_xor_sync(0xffffffffu, v, o));
            if (h == 0) red[0] = v;
        }
        __syncthreads();
        float M = red[0];
        __syncthreads();
        float eg = expf(gar - M);
        float sm = eg;
        #pragma unroll
        for (int o = 16; o; o >>= 1) sm += __shfl_xor_sync(0xffffffffu, sm, o);
        if ((h & 31) == 0) red[h>>5] = sm;
        __syncthreads();
        if (h < 32){
            float v = (h < 8) ? red[h] : 0.0f;
            #pragma unroll
            for (int o = 4; o; o >>= 1) v += __shfl_xor_sync(0xffffffffu, v, o);
            if (h == 0) red[0] = v;
        }
        __syncthreads();
        float S = red[0];

        int ix = s*NH + h;
        g_kp[ix] = kp; g_ks[ix] = ks; g_kg[ix] = kg; g_gp[ix] = gp;
        g_gL[ix] = gL; g_qb[ix] = qb; g_ga[ix] = eg/S;
    } else {
        int s = blockIdx.x - NS;
        const float* rf = g_rfraw + s*(NH*NR) + h*NR;
        float v[NR];
        float m = -1e30f;
        #pragma unroll
        for (int j = 0; j < NR; j++){ v[j] = fmaxf(rf[j], 0.0f); m = fmaxf(m, v[j]); }
        float ssum = 0.0f;
        #pragma unroll
        for (int j = 0; j < NR; j++){ v[j] = expf(v[j]-m); ssum += v[j]; }
        float* out = g_r + s*(NH*NR) + h*NR;
        #pragma unroll
        for (int j = 0; j < NR; j++) out[j] = v[j]/ssum;
    }
}

// ============ fused reservoir scan (PF8, transposed Q) + 16-tap conv ========
__global__ void __launch_bounds__(256) scanconv_kernel(float* __restrict__ out){
    __shared__ float sPs[368];
    __shared__ float sQ[256*33];       // reused as yPart in phase B

    const int s = blockIdx.x, tid = threadIdx.x, h = tid;

    for (int i = tid; i < NT; i += 256) sPs[i] = g_PsT[s*QSTR + i];

    const int idx0 = (s << 8) + h;
    const float kp = g_kp[idx0], ks = g_ks[idx0], kg = g_kg[idx0];
    const float gp = g_gp[idx0], gL = g_gL[idx0], qb = g_qb[idx0];
    __syncthreads();

    float Sf = 0.0f, Ss = 0.0f, Sg = 0.0f;
    const size_t str = (size_t)NS*NH;
    float fl[8], fev[8], fm[8];
    {
        size_t ix = idx0;
        #pragma unroll
        for (int i = 0; i < 8; i++){
            fl[i] = g_Pl[ix]; fev[i] = g_Ev[ix]; fm[i] = g_Vm[ix];
            ix += str;
        }
    }
    size_t ixn = (size_t)idx0 + 8*str;

    auto step = [&](int tt, float cfl, float cfev, float cfm){
        float fs = sPs[tt];
        float a  = Sf + fs;
        float qf = fminf(a, cfm);
        Sf = fmaxf(a - cfm, 0.0f);
        float H  = fmaxf(Ss + cfl + qf - cfev, 0.0f);
        float qp = fmaxf(kp*(H - gL), 0.0f);
        float qsa = ks*fminf(H, gL);
        Ss = H - qp - qsa;
        float sgin = Sg + qsa*gp;
        float qg = kg*sgin + qb;
        Sg = (1.0f - kg)*sgin - qb;
        return qp + qsa*(1.0f - gp) + qg;
    };
    auto flush = [&](int t0, int cnt){
        __syncthreads();
        #pragma unroll
        for (int it = 0; it < 32; it++){
            int u = tid + it*256;
            int hh = u >> 5, tt = u & 31;
            if (tt < cnt)
                g_Qt[(size_t)((s<<8)+hh)*QSTR + t0 + tt] = sQ[hh*33 + tt];
        }
        __syncthreads();
    };

    #pragma unroll 1
    for (int tb = 0; tb < 360; tb += 8){
        #pragma unroll
        for (int i = 0; i < 8; i++){
            int tt = tb + i;
            float cfl = fl[i], cfev = fev[i], cfm = fm[i];
            if (tt + 8 < NT){
                fl[i] = g_Pl[ixn]; fev[i] = g_Ev[ixn]; fm[i] = g_Vm[ixn];
                ixn += str;
            }
            float q = step(tt, cfl, cfev, cfm);
            sQ[h*33 + (tt & 31)] = q;
            if ((tt & 31) == 31) flush(tt - 31, 32);
        }
    }
    #pragma unroll
    for (int i = 0; i < 5; i++){
        int tt = 360 + i;
        float q = step(tt, fl[i], fev[i], fm[i]);
        sQ[h*33 + (tt & 31)] = q;
    }
    flush(352, 13);

    // ---- phase B: conv + ga-weighted reduce over h ----
    const int w = tid >> 5, lane = tid & 31;
    const int t0 = lane*11;
    float y[11];
    #pragma unroll
    for (int i = 0; i < 11; i++) y[i] = 0.0f;

    for (int hh = 0; hh < 32; hh++){
        int base = (s << 8) + w*32 + hh;
        float gah = g_ga[base];
        const float* rp = g_r + (size_t)base*NR;
        float c[16];
        #pragma unroll
        for (int j = 0; j < 16; j++) c[j] = gah*rp[j];
        const float* qp2 = g_Qt + (size_t)base*QSTR + t0;
        float q[26];
        #pragma unroll
        for (int u = 0; u < 26; u++) q[u] = (t0 + u < NT) ? qp2[u] : 0.0f;
        #pragma unroll
        for (int i = 0; i < 11; i++){
            float acc = y[i];
            #pragma unroll
            for (int j = 0; j < 16; j++) acc += c[j]*q[i+j];
            y[i] = acc;
        }
    }
    float* yP = sQ;
    #pragma unroll
    for (int i = 0; i < 11; i++) yP[w*352 + t0 + i] = y[i];
    __syncthreads();
    for (int t = tid; t < TOUT; t += 256){
        float acc = 0.0f;
        #pragma unroll
        for (int w2 = 0; w2 < 8; w2++) acc += yP[w2*352 + t];
        out[t*NS + s] = acc;
    }
}

// ---------------- launch ----------------------------------------------------
extern "C" void kernel_launch(void* const* d_in, const int* in_sizes, int n_in,
                              void* d_out, int out_size){
    const float* x      = (const float*)d_in[0];
    const float* xc     = (const float*)d_in[1];
    const float* fcW_w1 = (const float*)d_in[2];
    const float* fcW_b1 = (const float*)d_in[3];
    const float* fcW_w2 = (const float*)d_in[4];
    const float* fcW_b2 = (const float*)d_in[5];
    const float* fcT_w1 = (const float*)d_in[6];
    const float* fcT_b1 = (const float*)d_in[7];
    const float* fcT_w2 = (const float*)d_in[8];
    const float* fcT_b2 = (const float*)d_in[9];
    const float* fcR_w1 = (const float*)d_in[10];
    const float* fcR_b1 = (const float*)d_in[11];
    const float* fcR_w2 = (const float*)d_in[12];
    const float* fcR_b2 = (const float*)d_in[13];
    float* out = (float*)d_out;

    cudaFuncSetAttribute(gemmMMA_kernel, cudaFuncAttributeMaxDynamicSharedMemorySize, SMEM_MMA);

    setup_kernel<<<365+192+768, 256>>>(x, xc, fcT_w2, fcW_w1, fcW_b1, fcR_w1, fcR_b1, fcT_w1, fcT_b1);
    gemmWR_kernel<<<dim3(92, 2), 256>>>(fcW_w2, fcW_b2, fcR_w2, fcR_b2);
    actWR_kernel<<<2*NS, 256>>>();
    hiddenT_kernel<<<NTS/2, 256>>>(x, fcT_w1);
    gemmMMA_kernel<<<dim3(6, MTILES), 256, SMEM_MMA>>>(fcT_b2, x);
    scanconv_kernel<<<NS, 256>>>(out);
}